// round 1
// baseline (speedup 1.0000x reference)
#include <cuda_runtime.h>
#include <math.h>

// Problem constants
#define BATCH 8
#define NN    2048
#define DD    256
#define MT    (BATCH * NN)      // 16384 total rows
#define G3    (3 * DD)          // 768

// ---------------------------------------------------------------------------
// Scratch: __device__ globals (no allocation allowed in kernel_launch)
// ---------------------------------------------------------------------------
__device__ float g_xn[MT * DD];                     // normalized x_topic  (16.8 MB)
__device__ float g_Wh[MT * DD];                     // x @ W               (16.8 MB)
__device__ float g_S[(size_t)BATCH * NN * NN];      // mask*exp(cos)       (134 MB)
__device__ float g_rowsum[MT];                      // row sums of S
__device__ float g_go[MT * DD];                     // graph_out           (16.8 MB)
__device__ float g_gi[MT * G3];                     // graph_out@W_ih^T+b  (50 MB)
__device__ float g_gh[MT * G3];                     // x@W_hh^T+b          (50 MB)

// ---------------------------------------------------------------------------
// Shared 128x128x16 fp32 GEMM tile, 256 threads, 8x8 per thread.
// Smem stored k-major: As[k][m], Bs[k][n] with +4 pad so compute-side reads
// are LDS.128 and stores are <=2-way conflicted.
// BT=true:  B is [Ncols, K] row-major (i.e. we compute A @ B^T)
// BT=false: B is [K, Ncols] row-major (plain A @ B)
// All dims must be multiples of the tile (true for every GEMM here).
// ---------------------------------------------------------------------------
template <bool BT>
__device__ __forceinline__ void gemm_block(
    const float* __restrict__ A, const float* __restrict__ B,
    int K, int lda, int ldb, float (&acc)[8][8])
{
    __shared__ float As[16][132];
    __shared__ float Bs[16][132];
    const int tid = threadIdx.x;
    const int tx = tid & 15;
    const int ty = tid >> 4;
    const size_t rowBase = (size_t)blockIdx.y * 128;
    const size_t colBase = (size_t)blockIdx.x * 128;

#pragma unroll
    for (int i = 0; i < 8; i++)
#pragma unroll
        for (int j = 0; j < 8; j++) acc[i][j] = 0.f;

    for (int k0 = 0; k0 < K; k0 += 16) {
        // ---- load A tile [128 x 16] (A row-major, k contiguous) ----
#pragma unroll
        for (int it = 0; it < 2; it++) {
            int idx4 = tid + it * 256;       // 512 float4 = 2048 floats
            int m  = idx4 >> 2;
            int kq = (idx4 & 3) * 4;
            float4 v = *reinterpret_cast<const float4*>(
                &A[(rowBase + m) * (size_t)lda + k0 + kq]);
            As[kq + 0][m] = v.x;
            As[kq + 1][m] = v.y;
            As[kq + 2][m] = v.z;
            As[kq + 3][m] = v.w;
        }
        // ---- load B tile ----
        if (BT) {
#pragma unroll
            for (int it = 0; it < 2; it++) {
                int idx4 = tid + it * 256;
                int n  = idx4 >> 2;
                int kq = (idx4 & 3) * 4;
                float4 v = *reinterpret_cast<const float4*>(
                    &B[(colBase + n) * (size_t)ldb + k0 + kq]);
                Bs[kq + 0][n] = v.x;
                Bs[kq + 1][n] = v.y;
                Bs[kq + 2][n] = v.z;
                Bs[kq + 3][n] = v.w;
            }
        } else {
#pragma unroll
            for (int it = 0; it < 2; it++) {
                int idx4 = tid + it * 256;
                int k  = idx4 >> 5;
                int n4 = (idx4 & 31) * 4;
                *reinterpret_cast<float4*>(&Bs[k][n4]) =
                    *reinterpret_cast<const float4*>(
                        &B[(size_t)(k0 + k) * ldb + colBase + n4]);
            }
        }
        __syncthreads();

        // ---- compute ----
#pragma unroll
        for (int kk = 0; kk < 16; kk++) {
            float4 a0 = *reinterpret_cast<const float4*>(&As[kk][ty * 8]);
            float4 a1 = *reinterpret_cast<const float4*>(&As[kk][ty * 8 + 4]);
            float4 b0 = *reinterpret_cast<const float4*>(&Bs[kk][tx * 8]);
            float4 b1 = *reinterpret_cast<const float4*>(&Bs[kk][tx * 8 + 4]);
            float ra[8] = {a0.x, a0.y, a0.z, a0.w, a1.x, a1.y, a1.z, a1.w};
            float rb[8] = {b0.x, b0.y, b0.z, b0.w, b1.x, b1.y, b1.z, b1.w};
#pragma unroll
            for (int i = 0; i < 8; i++)
#pragma unroll
                for (int j = 0; j < 8; j++)
                    acc[i][j] = fmaf(ra[i], rb[j], acc[i][j]);
        }
        __syncthreads();
    }
}

// ---------------------------------------------------------------------------
// Kernel 1: row-normalize x_topic  ->  g_xn
// ---------------------------------------------------------------------------
__global__ __launch_bounds__(256) void k_norm(const float* __restrict__ xt)
{
    size_t row = blockIdx.x;
    int d = threadIdx.x;
    float v = xt[row * DD + d];
    float s = v * v;
#pragma unroll
    for (int o = 16; o > 0; o >>= 1) s += __shfl_xor_sync(0xffffffffu, s, o);
    __shared__ float red[8];
    __shared__ float inv;
    if ((d & 31) == 0) red[d >> 5] = s;
    __syncthreads();
    if (d == 0) {
        float t = 0.f;
#pragma unroll
        for (int i = 0; i < 8; i++) t += red[i];
        inv = rsqrtf(fmaxf(t, 1e-30f));
    }
    __syncthreads();
    g_xn[row * DD + d] = v * inv;
}

// ---------------------------------------------------------------------------
// Kernel 2: Wh = x @ W      (A[16384,256] @ B[256,256], NN)
// ---------------------------------------------------------------------------
__global__ __launch_bounds__(256) void k_wh(const float* __restrict__ x,
                                            const float* __restrict__ W)
{
    float acc[8][8];
    gemm_block<false>(x, W, DD, DD, DD, acc);
    const size_t rowBase = (size_t)blockIdx.y * 128;
    const size_t colBase = (size_t)blockIdx.x * 128;
    const int tx = threadIdx.x & 15, ty = threadIdx.x >> 4;
#pragma unroll
    for (int i = 0; i < 8; i++) {
        size_t r = rowBase + ty * 8 + i;
#pragma unroll
        for (int j = 0; j < 8; j++)
            g_Wh[r * DD + colBase + tx * 8 + j] = acc[i][j];
    }
}

// ---------------------------------------------------------------------------
// Kernel 3: S[b,n,m] = (adj>0) ? exp(xn_n . xn_m) : 0   (A@A^T per batch, NT)
// (cos in [-1,1] => softmax needs no max subtraction)
// ---------------------------------------------------------------------------
__global__ __launch_bounds__(256) void k_scores(const int* __restrict__ adj)
{
    int b = blockIdx.z;
    const float* Xb = g_xn + (size_t)b * NN * DD;
    float acc[8][8];
    gemm_block<true>(Xb, Xb, DD, DD, DD, acc);
    const size_t rowBase = (size_t)blockIdx.y * 128;
    const size_t colBase = (size_t)blockIdx.x * 128;
    const int tx = threadIdx.x & 15, ty = threadIdx.x >> 4;
    const size_t base = (size_t)b * NN * NN;
#pragma unroll
    for (int i = 0; i < 8; i++) {
        size_t r = rowBase + ty * 8 + i;
#pragma unroll
        for (int j = 0; j < 8; j++) {
            size_t c = colBase + tx * 8 + j;
            size_t idx = base + r * NN + c;
            g_S[idx] = (adj[idx] > 0) ? __expf(acc[i][j]) : 0.f;
        }
    }
}

// ---------------------------------------------------------------------------
// Kernel 4: row sums of S
// ---------------------------------------------------------------------------
__global__ __launch_bounds__(256) void k_rowsum()
{
    size_t row = blockIdx.x;
    const float* Sr = g_S + row * NN;
    float s = 0.f;
    for (int j = threadIdx.x; j < NN; j += 256) s += Sr[j];
#pragma unroll
    for (int o = 16; o > 0; o >>= 1) s += __shfl_xor_sync(0xffffffffu, s, o);
    __shared__ float red[8];
    if ((threadIdx.x & 31) == 0) red[threadIdx.x >> 5] = s;
    __syncthreads();
    if (threadIdx.x == 0) {
        float t = 0.f;
#pragma unroll
        for (int i = 0; i < 8; i++) t += red[i];
        g_rowsum[row] = t;
    }
}

// ---------------------------------------------------------------------------
// Kernel 5: graph_out = (S @ Wh) / rowsum   per batch  (NN, K=2048)
// ---------------------------------------------------------------------------
__global__ __launch_bounds__(256) void k_go()
{
    int b = blockIdx.z;
    const float* Sb  = g_S  + (size_t)b * NN * NN;
    const float* Whb = g_Wh + (size_t)b * NN * DD;
    float acc[8][8];
    gemm_block<false>(Sb, Whb, NN, NN, DD, acc);
    const size_t rowBase = (size_t)blockIdx.y * 128;
    const size_t colBase = (size_t)blockIdx.x * 128;
    const int tx = threadIdx.x & 15, ty = threadIdx.x >> 4;
#pragma unroll
    for (int i = 0; i < 8; i++) {
        size_t r = rowBase + ty * 8 + i;
        float inv = 1.f / g_rowsum[(size_t)b * NN + r];
#pragma unroll
        for (int j = 0; j < 8; j++)
            g_go[((size_t)b * NN + r) * DD + colBase + tx * 8 + j] = acc[i][j] * inv;
    }
}

// ---------------------------------------------------------------------------
// Kernel 6: gates GEMM  out = A @ Wt^T + bias   (A[16384,256], Wt[768,256], NT)
// which==0: A=g_go, out=g_gi ; which==1: A=xin, out=g_gh
// ---------------------------------------------------------------------------
__global__ __launch_bounds__(256) void k_lin(const float* __restrict__ xin,
                                             const float* __restrict__ Wt,
                                             const float* __restrict__ bias,
                                             int which)
{
    const float* A = (which == 0) ? (const float*)g_go : xin;
    float*      out = (which == 0) ? g_gi : g_gh;
    float acc[8][8];
    gemm_block<true>(A, Wt, DD, DD, DD, acc);
    const size_t rowBase = (size_t)blockIdx.y * 128;
    const size_t colBase = (size_t)blockIdx.x * 128;
    const int tx = threadIdx.x & 15, ty = threadIdx.x >> 4;
#pragma unroll
    for (int i = 0; i < 8; i++) {
        size_t r = rowBase + ty * 8 + i;
#pragma unroll
        for (int j = 0; j < 8; j++) {
            size_t c = colBase + tx * 8 + j;
            out[r * G3 + c] = acc[i][j] + bias[c];
        }
    }
}

// ---------------------------------------------------------------------------
// Kernel 7: GRU gate fusion (gate order r, z, n)
// ---------------------------------------------------------------------------
__global__ __launch_bounds__(256) void k_gate(const float* __restrict__ x,
                                              float* __restrict__ out)
{
    size_t row = blockIdx.x;
    int d = threadIdx.x;
    const float* gi = g_gi + row * G3;
    const float* gh = g_gh + row * G3;
    float r = 1.f / (1.f + __expf(-(gi[d] + gh[d])));
    float z = 1.f / (1.f + __expf(-(gi[DD + d] + gh[DD + d])));
    float n = tanhf(gi[2 * DD + d] + r * gh[2 * DD + d]);
    float h = x[row * DD + d];
    out[row * DD + d] = (1.f - z) * n + z * h;
}

// ---------------------------------------------------------------------------
// Launch
// ---------------------------------------------------------------------------
extern "C" void kernel_launch(void* const* d_in, const int* in_sizes, int n_in,
                              void* d_out, int out_size)
{
    const int*   adj   = (const int*)  d_in[0];
    const float* x     = (const float*)d_in[1];
    const float* xt    = (const float*)d_in[2];
    const float* W     = (const float*)d_in[3];
    const float* W_ih  = (const float*)d_in[4];
    const float* W_hh  = (const float*)d_in[5];
    const float* b_ih  = (const float*)d_in[6];
    const float* b_hh  = (const float*)d_in[7];
    float* out = (float*)d_out;

    k_norm  <<<MT, 256>>>(xt);
    k_wh    <<<dim3(DD / 128, MT / 128, 1), 256>>>(x, W);
    k_scores<<<dim3(NN / 128, NN / 128, BATCH), 256>>>(adj);
    k_rowsum<<<MT, 256>>>();
    k_go    <<<dim3(DD / 128, NN / 128, BATCH), 256>>>();
    k_lin   <<<dim3(G3 / 128, MT / 128, 1), 256>>>(x, W_ih, b_ih, 0);
    k_lin   <<<dim3(G3 / 128, MT / 128, 1), 256>>>(x, W_hh, b_hh, 1);
    k_gate  <<<MT, 256>>>(x, out);
}

// round 3
// speedup vs baseline: 3.0106x; 3.0106x over previous
#include <cuda_runtime.h>
#include <cstdint>
#include <math.h>

#define BATCH 8
#define NN    2048
#define DD    256
#define MT    (BATCH * NN)
#define G3    (3 * DD)

// ---------------------------------------------------------------------------
// Scratch (device globals; no allocation allowed)
// ---------------------------------------------------------------------------
__device__ __align__(16) float g_xr [MT * DD];                 // tf32-rounded x
__device__ __align__(16) float g_xn [MT * DD];                 // normalized+rounded x_topic
__device__ __align__(16) float g_Wr [DD * DD];                 // rounded W
__device__ __align__(16) float g_Wih[G3 * DD];                 // rounded W_ih
__device__ __align__(16) float g_Whh[G3 * DD];                 // rounded W_hh
__device__ __align__(16) float g_Wh [MT * DD];                 // x@W (rounded)
__device__ __align__(16) float g_S  [(size_t)BATCH * NN * NN]; // mask*exp(cos) (rounded)
__device__ __align__(16) float g_rowsum[MT];
__device__ __align__(16) float g_go [MT * DD];                 // graph_out (rounded)
__device__ __align__(16) float g_gi [MT * G3];
__device__ __align__(16) float g_gh [MT * G3];

// ---------------------------------------------------------------------------
// Helpers (all plain sm_80-era PTX — no arch-accelerated features)
// ---------------------------------------------------------------------------
__device__ __forceinline__ uint32_t s2u(const void* p) {
    uint32_t a;
    asm("{ .reg .u64 t; cvta.to.shared.u64 t, %1; cvt.u32.u64 %0, t; }" : "=r"(a) : "l"(p));
    return a;
}
__device__ __forceinline__ float tf32r(float x) {
    uint32_t y;
    asm("cvt.rna.tf32.f32 %0, %1;" : "=r"(y) : "f"(x));
    return __uint_as_float(y);
}
__device__ __forceinline__ void cp16(uint32_t dst, const void* src) {
    asm volatile("cp.async.cg.shared.global [%0], [%1], 16;" :: "r"(dst), "l"(src));
}
__device__ __forceinline__ void mma8(float& c0, float& c1, float& c2, float& c3,
                                     uint32_t a0, uint32_t a1, uint32_t a2, uint32_t a3,
                                     uint32_t b0, uint32_t b1) {
    asm volatile(
        "mma.sync.aligned.m16n8k8.row.col.f32.tf32.tf32.f32 "
        "{%0,%1,%2,%3}, {%4,%5,%6,%7}, {%8,%9}, {%0,%1,%2,%3};"
        : "+f"(c0), "+f"(c1), "+f"(c2), "+f"(c3)
        : "r"(a0), "r"(a1), "r"(a2), "r"(a3), "r"(b0), "r"(b1));
}

// ---------------------------------------------------------------------------
// tf32 mma.sync GEMM, block 128x128, 8 warps (warp tile 64x32), K-chunk 32,
// double-buffered cp.async.
// MODE 0: Wh = x@W            (B layout NN: B[k][n])
// MODE 1: S  = mask*exp(A@A^T) (B layout NT: B[n][k])
// MODE 2: go = (S@Wh)/rowsum  (NN)
// MODE 3: lin = A@Wt^T + bias (NT)
// smem: A 2 stages x 128x36 fl; B 2 stages x (128x36 | 32x136) fl  (72 KB)
// ---------------------------------------------------------------------------
#define SMEM_TOTAL 73728

template <int MODE>
__global__ void __launch_bounds__(256, 2)
gemm_mma(const float* __restrict__ Ag, const float* __restrict__ Bg,
         float* __restrict__ Cg, const int* __restrict__ adjg,
         const float* __restrict__ rsg, const float* __restrict__ biasg,
         int K, int lda, int ldb, int ldc)
{
    constexpr bool BT = (MODE == 1 || MODE == 3);   // B is [n][k] (NT) vs [k][n] (NN)
    extern __shared__ __align__(16) float sm[];
    float* sA = sm;            // 2 * 4608 floats
    float* sB = sm + 9216;     // 2 * (4608 | 4352) floats

    const int tid = threadIdx.x, lane = tid & 31, wid = tid >> 5;
    const int wm = (wid & 1) * 64, wn = (wid >> 1) * 32;
    const size_t rowBase = (size_t)blockIdx.y * 128;
    const size_t colBase = (size_t)blockIdx.x * 128;
    const int b = blockIdx.z;

    const float* A = Ag;
    const float* B = Bg;
    if (MODE == 1) { A += (size_t)b * NN * DD; B = A; }
    if (MODE == 2) { A = Ag + (size_t)b * NN * NN; B = Bg + (size_t)b * NN * DD; }

    const uint32_t sAu = s2u(sA), sBu = s2u(sB);

    auto load_stage = [&](int s, int k0) {
        uint32_t da = sAu + (uint32_t)s * 18432u;
#pragma unroll
        for (int i = 0; i < 4; i++) {
            int c = tid + i * 256;
            int row = c >> 3, q = (c & 7) * 4;
            cp16(da + (uint32_t)(row * 36 + q) * 4u,
                 A + (rowBase + row) * (size_t)lda + k0 + q);
        }
        if (BT) {
            uint32_t db = sBu + (uint32_t)s * 18432u;
#pragma unroll
            for (int i = 0; i < 4; i++) {
                int c = tid + i * 256;
                int row = c >> 3, q = (c & 7) * 4;
                cp16(db + (uint32_t)(row * 36 + q) * 4u,
                     B + (colBase + row) * (size_t)ldb + k0 + q);
            }
        } else {
            uint32_t db = sBu + (uint32_t)s * 17408u;
#pragma unroll
            for (int i = 0; i < 4; i++) {
                int c = tid + i * 256;
                int row = c >> 5, q = (c & 31) * 4;
                cp16(db + (uint32_t)(row * 136 + q) * 4u,
                     B + (size_t)(k0 + row) * ldb + colBase + q);
            }
        }
    };

    float acc[4][4][4];
#pragma unroll
    for (int mi = 0; mi < 4; mi++)
#pragma unroll
        for (int ni = 0; ni < 4; ni++)
#pragma unroll
            for (int j = 0; j < 4; j++) acc[mi][ni][j] = 0.f;

    load_stage(0, 0);
    asm volatile("cp.async.commit_group;");
    const int NCk = K / 32;
    for (int c = 0; c < NCk; c++) {
        if (c + 1 < NCk) load_stage((c + 1) & 1, (c + 1) * 32);
        asm volatile("cp.async.commit_group;");
        asm volatile("cp.async.wait_group 1;");
        __syncthreads();
        const float* As = sA + (c & 1) * 4608;
        const float* Bs = sB + (c & 1) * (BT ? 4608 : 4352);
#pragma unroll
        for (int ks = 0; ks < 4; ks++) {
            const int koff = ks * 8;
            const int ar = wm + (lane >> 2);
            const int ac = koff + (lane & 3);
            uint32_t af[4][4], bf[4][2];
#pragma unroll
            for (int mi = 0; mi < 4; mi++) {
                const float* p = As + (ar + mi * 16) * 36 + ac;
                af[mi][0] = __float_as_uint(p[0]);
                af[mi][1] = __float_as_uint(p[8 * 36]);
                af[mi][2] = __float_as_uint(p[4]);
                af[mi][3] = __float_as_uint(p[8 * 36 + 4]);
            }
#pragma unroll
            for (int ni = 0; ni < 4; ni++) {
                if (BT) {
                    const float* p = Bs + (wn + ni * 8 + (lane >> 2)) * 36 + ac;
                    bf[ni][0] = __float_as_uint(p[0]);
                    bf[ni][1] = __float_as_uint(p[4]);
                } else {
                    const float* p = Bs + (koff + (lane & 3)) * 136 + wn + ni * 8 + (lane >> 2);
                    bf[ni][0] = __float_as_uint(p[0]);
                    bf[ni][1] = __float_as_uint(p[4 * 136]);
                }
            }
#pragma unroll
            for (int mi = 0; mi < 4; mi++)
#pragma unroll
                for (int ni = 0; ni < 4; ni++)
                    mma8(acc[mi][ni][0], acc[mi][ni][1], acc[mi][ni][2], acc[mi][ni][3],
                         af[mi][0], af[mi][1], af[mi][2], af[mi][3],
                         bf[ni][0], bf[ni][1]);
        }
        __syncthreads();
    }

    // ---- epilogue: fragment layout c0=[r][c] c1=[r][c+1] c2=[r+8][c] c3=[r+8][c+1]
    float* Cb = Cg;
    if (MODE == 1) Cb = Cg + (size_t)b * NN * NN;
    if (MODE == 2) Cb = Cg + (size_t)b * NN * DD;
    const int gr = lane >> 2, gc2 = (lane & 3) * 2;

#pragma unroll
    for (int mi = 0; mi < 4; mi++) {
        size_t r0 = rowBase + wm + mi * 16 + gr;
        size_t r1 = r0 + 8;
        float inv0 = 1.f, inv1 = 1.f;
        if (MODE == 2) {
            inv0 = 1.f / rsg[(size_t)b * NN + r0];
            inv1 = 1.f / rsg[(size_t)b * NN + r1];
        }
#pragma unroll
        for (int ni = 0; ni < 4; ni++) {
            size_t cc = colBase + wn + ni * 8 + gc2;
            float v0 = acc[mi][ni][0], v1 = acc[mi][ni][1];
            float v2 = acc[mi][ni][2], v3 = acc[mi][ni][3];
            if (MODE == 0) {
                v0 = tf32r(v0); v1 = tf32r(v1); v2 = tf32r(v2); v3 = tf32r(v3);
            } else if (MODE == 1) {
                const int* ap = adjg + (size_t)b * NN * NN;
                int2 m0 = *(const int2*)(ap + r0 * NN + cc);
                int2 m1 = *(const int2*)(ap + r1 * NN + cc);
                v0 = (m0.x > 0) ? tf32r(__expf(v0)) : 0.f;
                v1 = (m0.y > 0) ? tf32r(__expf(v1)) : 0.f;
                v2 = (m1.x > 0) ? tf32r(__expf(v2)) : 0.f;
                v3 = (m1.y > 0) ? tf32r(__expf(v3)) : 0.f;
            } else if (MODE == 2) {
                v0 = tf32r(v0 * inv0); v1 = tf32r(v1 * inv0);
                v2 = tf32r(v2 * inv1); v3 = tf32r(v3 * inv1);
            } else {
                float b0 = biasg[cc], b1 = biasg[cc + 1];
                v0 += b0; v1 += b1; v2 += b0; v3 += b1;
            }
            float2 o0; o0.x = v0; o0.y = v1;
            float2 o1; o1.x = v2; o1.y = v3;
            *(float2*)(Cb + r0 * (size_t)ldc + cc) = o0;
            *(float2*)(Cb + r1 * (size_t)ldc + cc) = o1;
        }
    }
}

// ---------------------------------------------------------------------------
// Elementwise kernels
// ---------------------------------------------------------------------------
__global__ __launch_bounds__(256) void k_round4(const float* __restrict__ src,
                                                float* __restrict__ dst, int n4)
{
    int i = blockIdx.x * 256 + threadIdx.x;
    if (i < n4) {
        float4 v = ((const float4*)src)[i];
        v.x = tf32r(v.x); v.y = tf32r(v.y); v.z = tf32r(v.z); v.w = tf32r(v.w);
        ((float4*)dst)[i] = v;
    }
}

__global__ __launch_bounds__(256) void k_norm(const float* __restrict__ xt)
{
    size_t row = blockIdx.x;
    int d = threadIdx.x;
    float v = xt[row * DD + d];
    float s = v * v;
#pragma unroll
    for (int o = 16; o > 0; o >>= 1) s += __shfl_xor_sync(0xffffffffu, s, o);
    __shared__ float red[8];
    __shared__ float invs;
    if ((d & 31) == 0) red[d >> 5] = s;
    __syncthreads();
    if (d == 0) {
        float t = 0.f;
#pragma unroll
        for (int i = 0; i < 8; i++) t += red[i];
        invs = rsqrtf(fmaxf(t, 1e-30f));
    }
    __syncthreads();
    g_xn[row * DD + d] = tf32r(v * invs);
}

__global__ __launch_bounds__(256) void k_rowsum()
{
    size_t row = blockIdx.x;
    const float4* Sr = (const float4*)(g_S + row * NN);
    float s = 0.f;
#pragma unroll
    for (int i = 0; i < 2; i++) {
        float4 v = Sr[threadIdx.x + i * 256];
        s += (v.x + v.y) + (v.z + v.w);
    }
#pragma unroll
    for (int o = 16; o > 0; o >>= 1) s += __shfl_xor_sync(0xffffffffu, s, o);
    __shared__ float red[8];
    if ((threadIdx.x & 31) == 0) red[threadIdx.x >> 5] = s;
    __syncthreads();
    if (threadIdx.x == 0) {
        float t = 0.f;
#pragma unroll
        for (int i = 0; i < 8; i++) t += red[i];
        g_rowsum[row] = t;
    }
}

__global__ __launch_bounds__(256) void k_gate(const float* __restrict__ x,
                                              float* __restrict__ out)
{
    size_t row = blockIdx.x;
    int d = threadIdx.x;
    const float* gi = g_gi + row * G3;
    const float* gh = g_gh + row * G3;
    float r = 1.f / (1.f + __expf(-(gi[d] + gh[d])));
    float z = 1.f / (1.f + __expf(-(gi[DD + d] + gh[DD + d])));
    float n = tanhf(gi[2 * DD + d] + r * gh[2 * DD + d]);
    float h = x[row * DD + d];
    out[row * DD + d] = (1.f - z) * n + z * h;
}

// ---------------------------------------------------------------------------
// Launch
// ---------------------------------------------------------------------------
extern "C" void kernel_launch(void* const* d_in, const int* in_sizes, int n_in,
                              void* d_out, int out_size)
{
    const int*   adj  = (const int*)  d_in[0];
    const float* x    = (const float*)d_in[1];
    const float* xt   = (const float*)d_in[2];
    const float* W    = (const float*)d_in[3];
    const float* W_ih = (const float*)d_in[4];
    const float* W_hh = (const float*)d_in[5];
    const float* b_ih = (const float*)d_in[6];
    const float* b_hh = (const float*)d_in[7];
    float* out = (float*)d_out;

    cudaFuncSetAttribute(gemm_mma<0>, cudaFuncAttributeMaxDynamicSharedMemorySize, SMEM_TOTAL);
    cudaFuncSetAttribute(gemm_mma<1>, cudaFuncAttributeMaxDynamicSharedMemorySize, SMEM_TOTAL);
    cudaFuncSetAttribute(gemm_mma<2>, cudaFuncAttributeMaxDynamicSharedMemorySize, SMEM_TOTAL);
    cudaFuncSetAttribute(gemm_mma<3>, cudaFuncAttributeMaxDynamicSharedMemorySize, SMEM_TOTAL);

    float* xr  = nullptr; cudaGetSymbolAddress((void**)&xr,  g_xr);
    float* xn  = nullptr; cudaGetSymbolAddress((void**)&xn,  g_xn);
    float* Wr  = nullptr; cudaGetSymbolAddress((void**)&Wr,  g_Wr);
    float* Wih = nullptr; cudaGetSymbolAddress((void**)&Wih, g_Wih);
    float* Whh = nullptr; cudaGetSymbolAddress((void**)&Whh, g_Whh);
    float* Wh  = nullptr; cudaGetSymbolAddress((void**)&Wh,  g_Wh);
    float* S   = nullptr; cudaGetSymbolAddress((void**)&S,   g_S);
    float* rs  = nullptr; cudaGetSymbolAddress((void**)&rs,  g_rowsum);
    float* go  = nullptr; cudaGetSymbolAddress((void**)&go,  g_go);
    float* gi  = nullptr; cudaGetSymbolAddress((void**)&gi,  g_gi);
    float* gh  = nullptr; cudaGetSymbolAddress((void**)&gh,  g_gh);

    // tf32-round all GEMM inputs once (mma.sync truncates; rna kills bias)
    k_round4<<<(MT * DD / 4 + 255) / 256, 256>>>(x,    xr,  MT * DD / 4);
    k_round4<<<(DD * DD / 4 + 255) / 256, 256>>>(W,    Wr,  DD * DD / 4);
    k_round4<<<(G3 * DD / 4 + 255) / 256, 256>>>(W_ih, Wih, G3 * DD / 4);
    k_round4<<<(G3 * DD / 4 + 255) / 256, 256>>>(W_hh, Whh, G3 * DD / 4);
    k_norm<<<MT, 256>>>(xt);

    // Wh = x @ W   (NN)
    gemm_mma<0><<<dim3(DD / 128, MT / 128, 1), 256, SMEM_TOTAL>>>(
        xr, Wr, Wh, nullptr, nullptr, nullptr, DD, DD, DD, DD);
    // S = mask * exp(xn @ xn^T)  per batch (NT)
    gemm_mma<1><<<dim3(NN / 128, NN / 128, BATCH), 256, SMEM_TOTAL>>>(
        xn, xn, S, adj, nullptr, nullptr, DD, DD, DD, NN);
    k_rowsum<<<MT, 256>>>();
    // go = (S @ Wh) / rowsum  per batch (NN)
    gemm_mma<2><<<dim3(DD / 128, NN / 128, BATCH), 256, SMEM_TOTAL>>>(
        S, Wh, go, nullptr, rs, nullptr, NN, NN, DD, DD);
    // gi = go @ W_ih^T + b_ih ; gh = x @ W_hh^T + b_hh  (NT)
    gemm_mma<3><<<dim3(G3 / 128, MT / 128, 1), 256, SMEM_TOTAL>>>(
        go, Wih, gi, nullptr, nullptr, b_ih, DD, DD, DD, G3);
    gemm_mma<3><<<dim3(G3 / 128, MT / 128, 1), 256, SMEM_TOTAL>>>(
        xr, Whh, gh, nullptr, nullptr, b_hh, DD, DD, DD, G3);
    k_gate<<<MT, 256>>>(x, out);
}

// round 4
// speedup vs baseline: 3.0775x; 1.0222x over previous
#include <cuda_runtime.h>
#include <cstdint>
#include <math.h>

#define BATCH 8
#define NN    2048
#define DD    256
#define MT    (BATCH * NN)
#define G3    (3 * DD)
#define NTILE 16                 // NN/128 column tiles per row (for rowsum partials)

// ---------------------------------------------------------------------------
// Scratch (device globals; no allocation allowed)
// ---------------------------------------------------------------------------
__device__ __align__(16) float g_xr [MT * DD];
__device__ __align__(16) float g_xn [MT * DD];
__device__ __align__(16) float g_Wr [DD * DD];
__device__ __align__(16) float g_Wih[G3 * DD];
__device__ __align__(16) float g_Whh[G3 * DD];
__device__ __align__(16) float g_Wh [MT * DD];
__device__ __align__(16) float g_S  [(size_t)BATCH * NN * NN];
__device__ __align__(16) float g_rspart[NTILE * MT];
__device__ __align__(16) float g_rowsum[MT];
__device__ __align__(16) float g_go [MT * DD];
__device__ __align__(16) float g_gi [MT * G3];
__device__ __align__(16) float g_gh [MT * G3];

// ---------------------------------------------------------------------------
// Helpers (plain sm_80-era PTX only — target is compute_103, no 'a' features)
// ---------------------------------------------------------------------------
__device__ __forceinline__ uint32_t s2u(const void* p) {
    uint32_t a;
    asm("{ .reg .u64 t; cvta.to.shared.u64 t, %1; cvt.u32.u64 %0, t; }" : "=r"(a) : "l"(p));
    return a;
}
__device__ __forceinline__ float tf32r(float x) {
    uint32_t y;
    asm("cvt.rna.tf32.f32 %0, %1;" : "=r"(y) : "f"(x));
    return __uint_as_float(y);
}
__device__ __forceinline__ void cp16(uint32_t dst, const void* src) {
    asm volatile("cp.async.cg.shared.global [%0], [%1], 16;" :: "r"(dst), "l"(src));
}
__device__ __forceinline__ void mma8(float& c0, float& c1, float& c2, float& c3,
                                     uint32_t a0, uint32_t a1, uint32_t a2, uint32_t a3,
                                     uint32_t b0, uint32_t b1) {
    asm volatile(
        "mma.sync.aligned.m16n8k8.row.col.f32.tf32.tf32.f32 "
        "{%0,%1,%2,%3}, {%4,%5,%6,%7}, {%8,%9}, {%0,%1,%2,%3};"
        : "+f"(c0), "+f"(c1), "+f"(c2), "+f"(c3)
        : "r"(a0), "r"(a1), "r"(a2), "r"(a3), "r"(b0), "r"(b1));
}

// ---------------------------------------------------------------------------
// tf32 mma.sync GEMM, block 128x128, 4 warps (warp tile 64x64), K-chunk 32,
// double-buffered cp.async. 1.0 LDS per MMA.
// MODE 0: Wh = x@W              (B layout NN: B[k][n]), round output
// MODE 1: S  = mask*exp(A@A^T)  (NT), round output, emit row-sum partials
// MODE 2: go = (S@Wh)/rowsum    (NN), round output
// MODE 3: lin = A@Wt^T + bias   (NT); blockIdx.z selects (go,Wih,gi,b_ih) /
//                                                      (xr,Whh,gh,b_hh)
// ---------------------------------------------------------------------------
#define SMEM_TOTAL 73728

template <int MODE>
__global__ void __launch_bounds__(128)
gemm_mma(const float* __restrict__ Ag, const float* __restrict__ Bg,
         float* __restrict__ Cg, const int* __restrict__ adjg,
         const float* __restrict__ rsg, const float* __restrict__ biasg,
         const float* __restrict__ A2, const float* __restrict__ B2,
         float* __restrict__ C2, const float* __restrict__ bias2,
         int K, int lda, int ldb, int ldc)
{
    constexpr bool BT = (MODE == 1 || MODE == 3);
    extern __shared__ __align__(16) float sm[];
    float* sA = sm;            // 2 * 4608 floats
    float* sB = sm + 9216;     // 2 * (4608 | 4352) floats

    const int tid = threadIdx.x, lane = tid & 31, wid = tid >> 5;
    const int wm = (wid & 1) * 64, wn = (wid >> 1) * 64;
    const size_t rowBase = (size_t)blockIdx.y * 128;
    const size_t colBase = (size_t)blockIdx.x * 128;
    const int b = blockIdx.z;

    const float* A = Ag;
    const float* B = Bg;
    float* Cb = Cg;
    const float* bias = biasg;
    if (MODE == 1) { A = Ag + (size_t)b * NN * DD; B = A; Cb = Cg + (size_t)b * NN * NN; }
    if (MODE == 2) { A = Ag + (size_t)b * NN * NN; B = Bg + (size_t)b * NN * DD;
                     Cb = Cg + (size_t)b * NN * DD; }
    if (MODE == 3 && b == 1) { A = A2; B = B2; Cb = C2; bias = bias2; }

    const uint32_t sAu = s2u(sA), sBu = s2u(sB);

    auto load_stage = [&](int s, int k0) {
        uint32_t da = sAu + (uint32_t)s * 18432u;
#pragma unroll
        for (int i = 0; i < 8; i++) {
            int c = tid + i * 128;
            int row = c >> 3, q = (c & 7) * 4;
            cp16(da + (uint32_t)(row * 36 + q) * 4u,
                 A + (rowBase + row) * (size_t)lda + k0 + q);
        }
        if (BT) {
            uint32_t db = sBu + (uint32_t)s * 18432u;
#pragma unroll
            for (int i = 0; i < 8; i++) {
                int c = tid + i * 128;
                int row = c >> 3, q = (c & 7) * 4;
                cp16(db + (uint32_t)(row * 36 + q) * 4u,
                     B + (colBase + row) * (size_t)ldb + k0 + q);
            }
        } else {
            uint32_t db = sBu + (uint32_t)s * 17408u;
#pragma unroll
            for (int i = 0; i < 8; i++) {
                int c = tid + i * 128;
                int row = c >> 5, q = (c & 31) * 4;
                cp16(db + (uint32_t)(row * 136 + q) * 4u,
                     B + (size_t)(k0 + row) * ldb + colBase + q);
            }
        }
    };

    float acc[4][8][4];
#pragma unroll
    for (int mi = 0; mi < 4; mi++)
#pragma unroll
        for (int ni = 0; ni < 8; ni++)
#pragma unroll
            for (int j = 0; j < 4; j++) acc[mi][ni][j] = 0.f;

    load_stage(0, 0);
    asm volatile("cp.async.commit_group;");
    const int NCk = K / 32;
    for (int c = 0; c < NCk; c++) {
        if (c + 1 < NCk) load_stage((c + 1) & 1, (c + 1) * 32);
        asm volatile("cp.async.commit_group;");
        asm volatile("cp.async.wait_group 1;");
        __syncthreads();
        const float* As = sA + (c & 1) * 4608;
        const float* Bs = sB + (c & 1) * (BT ? 4608 : 4352);
#pragma unroll
        for (int ks = 0; ks < 4; ks++) {
            const int koff = ks * 8;
            const int ar = wm + (lane >> 2);
            const int ac = koff + (lane & 3);
            uint32_t af[4][4], bf[8][2];
#pragma unroll
            for (int mi = 0; mi < 4; mi++) {
                const float* p = As + (ar + mi * 16) * 36 + ac;
                af[mi][0] = __float_as_uint(p[0]);
                af[mi][1] = __float_as_uint(p[8 * 36]);
                af[mi][2] = __float_as_uint(p[4]);
                af[mi][3] = __float_as_uint(p[8 * 36 + 4]);
            }
#pragma unroll
            for (int ni = 0; ni < 8; ni++) {
                if (BT) {
                    const float* p = Bs + (wn + ni * 8 + (lane >> 2)) * 36 + ac;
                    bf[ni][0] = __float_as_uint(p[0]);
                    bf[ni][1] = __float_as_uint(p[4]);
                } else {
                    const float* p = Bs + (koff + (lane & 3)) * 136 + wn + ni * 8 + (lane >> 2);
                    bf[ni][0] = __float_as_uint(p[0]);
                    bf[ni][1] = __float_as_uint(p[4 * 136]);
                }
            }
#pragma unroll
            for (int mi = 0; mi < 4; mi++)
#pragma unroll
                for (int ni = 0; ni < 8; ni++)
                    mma8(acc[mi][ni][0], acc[mi][ni][1], acc[mi][ni][2], acc[mi][ni][3],
                         af[mi][0], af[mi][1], af[mi][2], af[mi][3],
                         bf[ni][0], bf[ni][1]);
        }
        __syncthreads();
    }

    // ---- epilogue (c0=[r][c] c1=[r][c+1] c2=[r+8][c] c3=[r+8][c+1]) ----
    const int gr = lane >> 2, gc2 = (lane & 3) * 2;
    float* spart = sA;   // reuse: [2][128] row-sum partials (MODE 1)

#pragma unroll
    for (int mi = 0; mi < 4; mi++) {
        size_t r0 = rowBase + wm + mi * 16 + gr;
        size_t r1 = r0 + 8;
        float inv0 = 1.f, inv1 = 1.f;
        if (MODE == 2) {
            inv0 = 1.f / rsg[(size_t)b * NN + r0];
            inv1 = 1.f / rsg[(size_t)b * NN + r1];
        }
        float sum0 = 0.f, sum1 = 0.f;
#pragma unroll
        for (int ni = 0; ni < 8; ni++) {
            size_t cc = colBase + wn + ni * 8 + gc2;
            float v0 = acc[mi][ni][0], v1 = acc[mi][ni][1];
            float v2 = acc[mi][ni][2], v3 = acc[mi][ni][3];
            if (MODE == 0) {
                v0 = tf32r(v0); v1 = tf32r(v1); v2 = tf32r(v2); v3 = tf32r(v3);
            } else if (MODE == 1) {
                const int* ap = adjg + (size_t)b * NN * NN;
                int2 m0 = *(const int2*)(ap + r0 * NN + cc);
                int2 m1 = *(const int2*)(ap + r1 * NN + cc);
                v0 = (m0.x > 0) ? tf32r(__expf(v0)) : 0.f;
                v1 = (m0.y > 0) ? tf32r(__expf(v1)) : 0.f;
                v2 = (m1.x > 0) ? tf32r(__expf(v2)) : 0.f;
                v3 = (m1.y > 0) ? tf32r(__expf(v3)) : 0.f;
                sum0 += v0 + v1;
                sum1 += v2 + v3;
            } else if (MODE == 2) {
                v0 = tf32r(v0 * inv0); v1 = tf32r(v1 * inv0);
                v2 = tf32r(v2 * inv1); v3 = tf32r(v3 * inv1);
            } else {
                float b0 = bias[cc], b1 = bias[cc + 1];
                v0 += b0; v1 += b1; v2 += b0; v3 += b1;
            }
            float2 o0; o0.x = v0; o0.y = v1;
            float2 o1; o1.x = v2; o1.y = v3;
            *(float2*)(Cb + r0 * (size_t)ldc + cc) = o0;
            *(float2*)(Cb + r1 * (size_t)ldc + cc) = o1;
        }
        if (MODE == 1) {
            sum0 += __shfl_xor_sync(0xffffffffu, sum0, 1);
            sum0 += __shfl_xor_sync(0xffffffffu, sum0, 2);
            sum1 += __shfl_xor_sync(0xffffffffu, sum1, 1);
            sum1 += __shfl_xor_sync(0xffffffffu, sum1, 2);
            if ((lane & 3) == 0) {
                spart[(wid >> 1) * 128 + wm + mi * 16 + gr]     = sum0;
                spart[(wid >> 1) * 128 + wm + mi * 16 + gr + 8] = sum1;
            }
        }
    }
    if (MODE == 1) {
        __syncthreads();
        if (tid < 128) {
            float s = spart[tid] + spart[128 + tid];
            g_rspart[(size_t)blockIdx.x * MT + (size_t)b * NN + rowBase + tid] = s;
        }
    }
}

// ---------------------------------------------------------------------------
// Elementwise kernels
// ---------------------------------------------------------------------------
__global__ __launch_bounds__(256) void k_round4(const float* __restrict__ src,
                                                float* __restrict__ dst, int n4)
{
    int i = blockIdx.x * 256 + threadIdx.x;
    if (i < n4) {
        float4 v = ((const float4*)src)[i];
        v.x = tf32r(v.x); v.y = tf32r(v.y); v.z = tf32r(v.z); v.w = tf32r(v.w);
        ((float4*)dst)[i] = v;
    }
}

__global__ __launch_bounds__(256) void k_norm(const float* __restrict__ xt)
{
    size_t row = blockIdx.x;
    int d = threadIdx.x;
    float v = xt[row * DD + d];
    float s = v * v;
#pragma unroll
    for (int o = 16; o > 0; o >>= 1) s += __shfl_xor_sync(0xffffffffu, s, o);
    __shared__ float red[8];
    __shared__ float invs;
    if ((d & 31) == 0) red[d >> 5] = s;
    __syncthreads();
    if (d == 0) {
        float t = 0.f;
#pragma unroll
        for (int i = 0; i < 8; i++) t += red[i];
        invs = rsqrtf(fmaxf(t, 1e-30f));
    }
    __syncthreads();
    g_xn[row * DD + d] = tf32r(v * invs);
}

__global__ __launch_bounds__(256) void k_rsred()
{
    int r = blockIdx.x * 256 + threadIdx.x;
    float s = 0.f;
#pragma unroll
    for (int t = 0; t < NTILE; t++) s += g_rspart[(size_t)t * MT + r];
    g_rowsum[r] = s;
}

__global__ __launch_bounds__(256) void k_gate(const float* __restrict__ x,
                                              float* __restrict__ out)
{
    size_t row = blockIdx.x;
    int d = threadIdx.x;
    const float* gi = g_gi + row * G3;
    const float* gh = g_gh + row * G3;
    float r = 1.f / (1.f + __expf(-(gi[d] + gh[d])));
    float z = 1.f / (1.f + __expf(-(gi[DD + d] + gh[DD + d])));
    float n = tanhf(gi[2 * DD + d] + r * gh[2 * DD + d]);
    float h = x[row * DD + d];
    out[row * DD + d] = (1.f - z) * n + z * h;
}

// ---------------------------------------------------------------------------
// Launch
// ---------------------------------------------------------------------------
extern "C" void kernel_launch(void* const* d_in, const int* in_sizes, int n_in,
                              void* d_out, int out_size)
{
    const int*   adj  = (const int*)  d_in[0];
    const float* x    = (const float*)d_in[1];
    const float* xt   = (const float*)d_in[2];
    const float* W    = (const float*)d_in[3];
    const float* W_ih = (const float*)d_in[4];
    const float* W_hh = (const float*)d_in[5];
    const float* b_ih = (const float*)d_in[6];
    const float* b_hh = (const float*)d_in[7];
    float* out = (float*)d_out;

    cudaFuncSetAttribute(gemm_mma<0>, cudaFuncAttributeMaxDynamicSharedMemorySize, SMEM_TOTAL);
    cudaFuncSetAttribute(gemm_mma<1>, cudaFuncAttributeMaxDynamicSharedMemorySize, SMEM_TOTAL);
    cudaFuncSetAttribute(gemm_mma<2>, cudaFuncAttributeMaxDynamicSharedMemorySize, SMEM_TOTAL);
    cudaFuncSetAttribute(gemm_mma<3>, cudaFuncAttributeMaxDynamicSharedMemorySize, SMEM_TOTAL);

    float* xr  = nullptr; cudaGetSymbolAddress((void**)&xr,  g_xr);
    float* xn  = nullptr; cudaGetSymbolAddress((void**)&xn,  g_xn);
    float* Wr  = nullptr; cudaGetSymbolAddress((void**)&Wr,  g_Wr);
    float* Wih = nullptr; cudaGetSymbolAddress((void**)&Wih, g_Wih);
    float* Whh = nullptr; cudaGetSymbolAddress((void**)&Whh, g_Whh);
    float* Wh  = nullptr; cudaGetSymbolAddress((void**)&Wh,  g_Wh);
    float* S   = nullptr; cudaGetSymbolAddress((void**)&S,   g_S);
    float* rs  = nullptr; cudaGetSymbolAddress((void**)&rs,  g_rowsum);
    float* go  = nullptr; cudaGetSymbolAddress((void**)&go,  g_go);
    float* gi  = nullptr; cudaGetSymbolAddress((void**)&gi,  g_gi);
    float* gh  = nullptr; cudaGetSymbolAddress((void**)&gh,  g_gh);

    // tf32-round all GEMM inputs once (mma.sync truncates; .rna kills bias)
    k_round4<<<(MT * DD / 4 + 255) / 256, 256>>>(x,    xr,  MT * DD / 4);
    k_round4<<<(DD * DD / 4 + 255) / 256, 256>>>(W,    Wr,  DD * DD / 4);
    k_round4<<<(G3 * DD / 4 + 255) / 256, 256>>>(W_ih, Wih, G3 * DD / 4);
    k_round4<<<(G3 * DD / 4 + 255) / 256, 256>>>(W_hh, Whh, G3 * DD / 4);
    k_norm<<<MT, 256>>>(xt);

    // Wh = x @ W   (NN)
    gemm_mma<0><<<dim3(DD / 128, MT / 128, 1), 128, SMEM_TOTAL>>>(
        xr, Wr, Wh, nullptr, nullptr, nullptr,
        nullptr, nullptr, nullptr, nullptr, DD, DD, DD, DD);
    // S = mask * exp(xn @ xn^T) per batch (NT) + row-sum partials
    gemm_mma<1><<<dim3(NN / 128, NN / 128, BATCH), 128, SMEM_TOTAL>>>(
        xn, xn, S, adj, nullptr, nullptr,
        nullptr, nullptr, nullptr, nullptr, DD, DD, DD, NN);
    k_rsred<<<MT / 256, 256>>>();
    // go = (S @ Wh) / rowsum per batch (NN)
    gemm_mma<2><<<dim3(DD / 128, NN / 128, BATCH), 128, SMEM_TOTAL>>>(
        S, Wh, go, nullptr, rs, nullptr,
        nullptr, nullptr, nullptr, nullptr, NN, NN, DD, DD);
    // gi = go @ W_ih^T + b_ih  ||  gh = x @ W_hh^T + b_hh   (NT, fused via z)
    gemm_mma<3><<<dim3(G3 / 128, MT / 128, 2), 128, SMEM_TOTAL>>>(
        go, Wih, gi, nullptr, nullptr, b_ih,
        xr, Whh, gh, b_hh, DD, DD, DD, G3);
    k_gate<<<MT, 256>>>(x, out);
}

// round 6
// speedup vs baseline: 4.6574x; 1.5134x over previous
#include <cuda_runtime.h>
#include <cuda_fp16.h>
#include <cstdint>
#include <math.h>

#define BATCH 8
#define NN    2048
#define DD    256
#define MT    (BATCH * NN)
#define G3    (3 * DD)
#define NTILE 16

// ---------------------------------------------------------------------------
// Scratch (device globals)
// ---------------------------------------------------------------------------
__device__ __align__(16) __half g_xh  [MT * DD];
__device__ __align__(16) __half g_xnh [MT * DD];
__device__ __align__(16) __half g_W16 [DD * DD];     // W  [k][n] fp16
__device__ __align__(16) __half g_Wihh[G3 * DD];     // W_ih [n][k]
__device__ __align__(16) __half g_Whhh[G3 * DD];     // W_hh [n][k]
__device__ __align__(16) __half g_WhO [MT * DD];     // x@W
__device__ __align__(16) __half g_S   [(size_t)BATCH * NN * NN];
__device__ __align__(16) float  g_rspart[NTILE * MT];
__device__ __align__(16) float  g_rowsum[MT];
__device__ __align__(16) __half g_go  [MT * DD];
__device__ __align__(16) __half g_gi  [MT * G3];
__device__ __align__(16) __half g_gh  [MT * G3];

// ---------------------------------------------------------------------------
// PTX helpers (sm_75/80-era only — target is compute_103, no 'a' features)
// ---------------------------------------------------------------------------
__device__ __forceinline__ uint32_t s2u(const void* p) {
    uint32_t a;
    asm("{ .reg .u64 t; cvta.to.shared.u64 t, %1; cvt.u32.u64 %0, t; }" : "=r"(a) : "l"(p));
    return a;
}
__device__ __forceinline__ void cp16(uint32_t dst, const void* src) {
    asm volatile("cp.async.cg.shared.global [%0], [%1], 16;" :: "r"(dst), "l"(src));
}
__device__ __forceinline__ void ldsm4(uint32_t& r0, uint32_t& r1, uint32_t& r2, uint32_t& r3,
                                      uint32_t a) {
    asm volatile("ldmatrix.sync.aligned.m8n8.x4.shared.b16 {%0,%1,%2,%3}, [%4];"
                 : "=r"(r0), "=r"(r1), "=r"(r2), "=r"(r3) : "r"(a));
}
__device__ __forceinline__ void ldsm4t(uint32_t& r0, uint32_t& r1, uint32_t& r2, uint32_t& r3,
                                       uint32_t a) {
    asm volatile("ldmatrix.sync.aligned.m8n8.x4.trans.shared.b16 {%0,%1,%2,%3}, [%4];"
                 : "=r"(r0), "=r"(r1), "=r"(r2), "=r"(r3) : "r"(a));
}
__device__ __forceinline__ void mma16(float& c0, float& c1, float& c2, float& c3,
                                      uint32_t a0, uint32_t a1, uint32_t a2, uint32_t a3,
                                      uint32_t b0, uint32_t b1) {
    asm volatile(
        "mma.sync.aligned.m16n8k16.row.col.f32.f16.f16.f32 "
        "{%0,%1,%2,%3}, {%4,%5,%6,%7}, {%8,%9}, {%0,%1,%2,%3};"
        : "+f"(c0), "+f"(c1), "+f"(c2), "+f"(c3)
        : "r"(a0), "r"(a1), "r"(a2), "r"(a3), "r"(b0), "r"(b1));
}

// ---------------------------------------------------------------------------
// fp16 mma.sync GEMM, block 128x128, 4 warps (warp tile 64x64), K-chunk 64,
// double-buffered cp.async, ldmatrix fragment loads.
// smem: A stages @0,@16K; B stages @32K,@48K (64 KB dynamic).
// Swizzle: 16B chunk index ^= (row & 7)  — conflict-free stores + ldmatrix.
// B fragments: BT ([n][k], identical layout to A) -> non-trans ldmatrix;
//              NN ([k][n]) -> trans ldmatrix (gives k-consecutive pairs).
// MODE 0: Wh = x@W              (NN: B[k][n])
// MODE 1: S  = mask*exp(A@A^T)  (NT: B[n][k]) + row-sum partials
// MODE 2: go = (S@Wh)/rowsum    (NN)
// MODE 3: lin = A@Wt^T + bias   (NT); blockIdx.z selects operand set
// ---------------------------------------------------------------------------
#define SMEM_TOTAL 65536

template <int MODE>
__global__ void __launch_bounds__(128)
gemm_h(const __half* __restrict__ Ag, const __half* __restrict__ Bg,
       __half* __restrict__ Cg, const int* __restrict__ adjg,
       const float* __restrict__ rsg, const float* __restrict__ biasg,
       const __half* __restrict__ A2, const __half* __restrict__ B2,
       __half* __restrict__ C2, const float* __restrict__ bias2,
       int K, int lda, int ldb, int ldc)
{
    constexpr bool BT = (MODE == 1 || MODE == 3);
    extern __shared__ __align__(16) char smdyn[];
    __shared__ float spart[256];
    const uint32_t smu = s2u(smdyn);

    const int tid = threadIdx.x, lane = tid & 31, wid = tid >> 5;
    const int wm = (wid & 1) * 64, wn = (wid >> 1) * 64;
    const size_t rowBase = (size_t)blockIdx.y * 128;
    const size_t colBase = (size_t)blockIdx.x * 128;
    const int b = blockIdx.z;

    const __half* A = Ag;
    const __half* B = Bg;
    __half* Cb = Cg;
    const float* bias = biasg;
    if (MODE == 1) { A = Ag + (size_t)b * NN * DD; B = A; Cb = Cg + (size_t)b * NN * NN; }
    if (MODE == 2) { A = Ag + (size_t)b * NN * NN; B = Bg + (size_t)b * NN * DD;
                     Cb = Cg + (size_t)b * NN * DD; }
    if (MODE == 3 && b == 1) { A = A2; B = B2; Cb = C2; bias = bias2; }

    auto load_stage = [&](int s, int k0) {
        uint32_t da = smu + (uint32_t)s * 16384u;
#pragma unroll
        for (int i = 0; i < 8; i++) {
            int c = tid + i * 128;
            int row = c >> 3, ch = c & 7;
            cp16(da + (uint32_t)(row * 128 + ((ch ^ (row & 7)) << 4)),
                 A + (rowBase + row) * (size_t)lda + k0 + ch * 8);
        }
        uint32_t db = smu + 32768u + (uint32_t)s * 16384u;
        if (BT) {
#pragma unroll
            for (int i = 0; i < 8; i++) {
                int c = tid + i * 128;
                int row = c >> 3, ch = c & 7;
                cp16(db + (uint32_t)(row * 128 + ((ch ^ (row & 7)) << 4)),
                     B + (colBase + row) * (size_t)ldb + k0 + ch * 8);
            }
        } else {
#pragma unroll
            for (int i = 0; i < 8; i++) {
                int c = tid + i * 128;
                int row = c >> 4, ch = c & 15;
                cp16(db + (uint32_t)(row * 256 + ((ch ^ (row & 7)) << 4)),
                     B + (size_t)(k0 + row) * ldb + colBase + ch * 8);
            }
        }
    };

    float acc[4][8][4];
#pragma unroll
    for (int mi = 0; mi < 4; mi++)
#pragma unroll
        for (int ni = 0; ni < 8; ni++)
#pragma unroll
            for (int j = 0; j < 4; j++) acc[mi][ni][j] = 0.f;

    load_stage(0, 0);
    asm volatile("cp.async.commit_group;");
    const int NCk = K / 64;
    for (int c = 0; c < NCk; c++) {
        if (c + 1 < NCk) load_stage((c + 1) & 1, (c + 1) * 64);
        asm volatile("cp.async.commit_group;");
        asm volatile("cp.async.wait_group 1;");
        __syncthreads();
        const uint32_t aB = smu + (uint32_t)(c & 1) * 16384u;
        const uint32_t bB = smu + 32768u + (uint32_t)(c & 1) * 16384u;
#pragma unroll
        for (int ks = 0; ks < 4; ks++) {
            uint32_t af[4][4], bf[8][2];
            {
                const int r0 = wm + (lane & 15);
                const int ch0 = 2 * ks + (lane >> 4);
#pragma unroll
                for (int mi = 0; mi < 4; mi++) {
                    int rr = r0 + mi * 16;
                    ldsm4(af[mi][0], af[mi][1], af[mi][2], af[mi][3],
                          aB + (uint32_t)(rr * 128 + ((ch0 ^ (rr & 7)) << 4)));
                }
            }
            if (BT) {
                // [n][k] tile == A layout: non-trans ldmatrix, A-style addressing.
                // r0=(n_lo,k_lo) r1=(n_hi,k_lo) r2=(n_lo,k_hi) r3=(n_hi,k_hi)
                const int n0 = wn + (lane & 15);
                const int ch = 2 * ks + (lane >> 4);
#pragma unroll
                for (int p = 0; p < 4; p++) {
                    int n = n0 + p * 16;
                    ldsm4(bf[2 * p][0], bf[2 * p + 1][0], bf[2 * p][1], bf[2 * p + 1][1],
                          bB + (uint32_t)(n * 128 + ((ch ^ (n & 7)) << 4)));
                }
            } else {
                // [k][n] tile: trans ldmatrix gives k-consecutive register pairs.
                const int k = ks * 16 + (lane & 7) + (((lane >> 3) & 1) << 3);
#pragma unroll
                for (int p = 0; p < 4; p++) {
                    int chn = ((wn + p * 16) >> 3) + (lane >> 4);
                    ldsm4t(bf[2 * p][0], bf[2 * p][1], bf[2 * p + 1][0], bf[2 * p + 1][1],
                           bB + (uint32_t)(k * 256 + ((chn ^ (k & 7)) << 4)));
                }
            }
#pragma unroll
            for (int mi = 0; mi < 4; mi++)
#pragma unroll
                for (int ni = 0; ni < 8; ni++)
                    mma16(acc[mi][ni][0], acc[mi][ni][1], acc[mi][ni][2], acc[mi][ni][3],
                          af[mi][0], af[mi][1], af[mi][2], af[mi][3],
                          bf[ni][0], bf[ni][1]);
        }
        __syncthreads();
    }

    // ---- epilogue (c0=[r][c] c1=[r][c+1] c2=[r+8][c] c3=[r+8][c+1]) ----
    const int gr = lane >> 2, gc2 = (lane & 3) * 2;

#pragma unroll
    for (int mi = 0; mi < 4; mi++) {
        size_t r0 = rowBase + wm + mi * 16 + gr;
        size_t r1 = r0 + 8;
        float inv0 = 1.f, inv1 = 1.f;
        if (MODE == 2) {
            inv0 = 1.f / rsg[(size_t)b * NN + r0];
            inv1 = 1.f / rsg[(size_t)b * NN + r1];
        }
        float sum0 = 0.f, sum1 = 0.f;
#pragma unroll
        for (int ni = 0; ni < 8; ni++) {
            size_t cc = colBase + wn + ni * 8 + gc2;
            float v0 = acc[mi][ni][0], v1 = acc[mi][ni][1];
            float v2 = acc[mi][ni][2], v3 = acc[mi][ni][3];
            if (MODE == 1) {
                const int* ap = adjg + (size_t)b * NN * NN;
                int2 m0 = *(const int2*)(ap + r0 * NN + cc);
                int2 m1 = *(const int2*)(ap + r1 * NN + cc);
                v0 = (m0.x > 0) ? __expf(v0) : 0.f;
                v1 = (m0.y > 0) ? __expf(v1) : 0.f;
                v2 = (m1.x > 0) ? __expf(v2) : 0.f;
                v3 = (m1.y > 0) ? __expf(v3) : 0.f;
            } else if (MODE == 2) {
                v0 *= inv0; v1 *= inv0; v2 *= inv1; v3 *= inv1;
            } else if (MODE == 3) {
                float b0 = bias[cc], b1 = bias[cc + 1];
                v0 += b0; v1 += b1; v2 += b0; v3 += b1;
            }
            __half2 h0 = __floats2half2_rn(v0, v1);
            __half2 h1 = __floats2half2_rn(v2, v3);
            *(__half2*)(Cb + r0 * (size_t)ldc + cc) = h0;
            *(__half2*)(Cb + r1 * (size_t)ldc + cc) = h1;
            if (MODE == 1) {
                // sum exactly the rounded values the go-GEMM will consume
                sum0 += __low2float(h0) + __high2float(h0);
                sum1 += __low2float(h1) + __high2float(h1);
            }
        }
        if (MODE == 1) {
            sum0 += __shfl_xor_sync(0xffffffffu, sum0, 1);
            sum0 += __shfl_xor_sync(0xffffffffu, sum0, 2);
            sum1 += __shfl_xor_sync(0xffffffffu, sum1, 1);
            sum1 += __shfl_xor_sync(0xffffffffu, sum1, 2);
            if ((lane & 3) == 0) {
                spart[(wid >> 1) * 128 + wm + mi * 16 + gr]     = sum0;
                spart[(wid >> 1) * 128 + wm + mi * 16 + gr + 8] = sum1;
            }
        }
    }
    if (MODE == 1) {
        __syncthreads();
        if (tid < 128) {
            float s = spart[tid] + spart[128 + tid];
            g_rspart[(size_t)blockIdx.x * MT + (size_t)b * NN + rowBase + tid] = s;
        }
    }
}

// ---------------------------------------------------------------------------
// Elementwise kernels
// ---------------------------------------------------------------------------
__global__ __launch_bounds__(256) void k_h4(const float* __restrict__ src,
                                            __half* __restrict__ dst, int n4)
{
    int i = blockIdx.x * 256 + threadIdx.x;
    if (i < n4) {
        float4 v = ((const float4*)src)[i];
        __half2 a = __floats2half2_rn(v.x, v.y);
        __half2 b = __floats2half2_rn(v.z, v.w);
        uint2 o;
        o.x = *(uint32_t*)&a;
        o.y = *(uint32_t*)&b;
        ((uint2*)dst)[i] = o;
    }
}

__global__ __launch_bounds__(256) void k_norm(const float* __restrict__ xt)
{
    size_t row = blockIdx.x;
    int d = threadIdx.x;
    float v = xt[row * DD + d];
    float s = v * v;
#pragma unroll
    for (int o = 16; o > 0; o >>= 1) s += __shfl_xor_sync(0xffffffffu, s, o);
    __shared__ float red[8];
    __shared__ float invs;
    if ((d & 31) == 0) red[d >> 5] = s;
    __syncthreads();
    if (d == 0) {
        float t = 0.f;
#pragma unroll
        for (int i = 0; i < 8; i++) t += red[i];
        invs = rsqrtf(fmaxf(t, 1e-30f));
    }
    __syncthreads();
    g_xnh[row * DD + d] = __float2half_rn(v * invs);
}

__global__ __launch_bounds__(256) void k_rsred()
{
    int r = blockIdx.x * 256 + threadIdx.x;
    float s = 0.f;
#pragma unroll
    for (int t = 0; t < NTILE; t++) s += g_rspart[(size_t)t * MT + r];
    g_rowsum[r] = s;
}

__global__ __launch_bounds__(256) void k_gate(const float* __restrict__ x,
                                              float* __restrict__ out)
{
    size_t row = blockIdx.x;
    int d = threadIdx.x;
    const __half* gi = g_gi + row * G3;
    const __half* gh = g_gh + row * G3;
    float r = 1.f / (1.f + __expf(-(__half2float(gi[d]) + __half2float(gh[d]))));
    float z = 1.f / (1.f + __expf(-(__half2float(gi[DD + d]) + __half2float(gh[DD + d]))));
    float n = tanhf(__half2float(gi[2 * DD + d]) + r * __half2float(gh[2 * DD + d]));
    float h = x[row * DD + d];
    out[row * DD + d] = (1.f - z) * n + z * h;
}

// ---------------------------------------------------------------------------
// Launch
// ---------------------------------------------------------------------------
extern "C" void kernel_launch(void* const* d_in, const int* in_sizes, int n_in,
                              void* d_out, int out_size)
{
    const int*   adj  = (const int*)  d_in[0];
    const float* x    = (const float*)d_in[1];
    const float* xt   = (const float*)d_in[2];
    const float* W    = (const float*)d_in[3];
    const float* W_ih = (const float*)d_in[4];
    const float* W_hh = (const float*)d_in[5];
    const float* b_ih = (const float*)d_in[6];
    const float* b_hh = (const float*)d_in[7];
    float* out = (float*)d_out;

    cudaFuncSetAttribute(gemm_h<0>, cudaFuncAttributeMaxDynamicSharedMemorySize, SMEM_TOTAL);
    cudaFuncSetAttribute(gemm_h<1>, cudaFuncAttributeMaxDynamicSharedMemorySize, SMEM_TOTAL);
    cudaFuncSetAttribute(gemm_h<2>, cudaFuncAttributeMaxDynamicSharedMemorySize, SMEM_TOTAL);
    cudaFuncSetAttribute(gemm_h<3>, cudaFuncAttributeMaxDynamicSharedMemorySize, SMEM_TOTAL);

    __half* xh  = nullptr; cudaGetSymbolAddress((void**)&xh,  g_xh);
    __half* xnh = nullptr; cudaGetSymbolAddress((void**)&xnh, g_xnh);
    __half* W16 = nullptr; cudaGetSymbolAddress((void**)&W16, g_W16);
    __half* Wih = nullptr; cudaGetSymbolAddress((void**)&Wih, g_Wihh);
    __half* Whh = nullptr; cudaGetSymbolAddress((void**)&Whh, g_Whhh);
    __half* WhO = nullptr; cudaGetSymbolAddress((void**)&WhO, g_WhO);
    __half* S   = nullptr; cudaGetSymbolAddress((void**)&S,   g_S);
    float*  rs  = nullptr; cudaGetSymbolAddress((void**)&rs,  g_rowsum);
    __half* go  = nullptr; cudaGetSymbolAddress((void**)&go,  g_go);
    __half* gi  = nullptr; cudaGetSymbolAddress((void**)&gi,  g_gi);
    __half* gh  = nullptr; cudaGetSymbolAddress((void**)&gh,  g_gh);

    // fp16 conversions
    k_h4<<<(MT * DD / 4 + 255) / 256, 256>>>(x,    xh,  MT * DD / 4);
    k_h4<<<(DD * DD / 4 + 255) / 256, 256>>>(W,    W16, DD * DD / 4);
    k_h4<<<(G3 * DD / 4 + 255) / 256, 256>>>(W_ih, Wih, G3 * DD / 4);
    k_h4<<<(G3 * DD / 4 + 255) / 256, 256>>>(W_hh, Whh, G3 * DD / 4);
    k_norm<<<MT, 256>>>(xt);

    // Wh = x @ W   (NN)
    gemm_h<0><<<dim3(DD / 128, MT / 128, 1), 128, SMEM_TOTAL>>>(
        xh, W16, WhO, nullptr, nullptr, nullptr,
        nullptr, nullptr, nullptr, nullptr, DD, DD, DD, DD);
    // S = mask * exp(xn @ xn^T) per batch (NT) + row-sum partials
    gemm_h<1><<<dim3(NN / 128, NN / 128, BATCH), 128, SMEM_TOTAL>>>(
        xnh, xnh, S, adj, nullptr, nullptr,
        nullptr, nullptr, nullptr, nullptr, DD, DD, DD, NN);
    k_rsred<<<MT / 256, 256>>>();
    // go = (S @ Wh) / rowsum per batch (NN)
    gemm_h<2><<<dim3(DD / 128, NN / 128, BATCH), 128, SMEM_TOTAL>>>(
        S, WhO, go, nullptr, rs, nullptr,
        nullptr, nullptr, nullptr, nullptr, NN, NN, DD, DD);
    // gi = go @ W_ih^T + b_ih || gh = x @ W_hh^T + b_hh  (NT, fused via z)
    gemm_h<3><<<dim3(G3 / 128, MT / 128, 2), 128, SMEM_TOTAL>>>(
        go, Wih, gi, nullptr, nullptr, b_ih,
        xh, Whh, gh, b_hh, DD, DD, DD, G3);
    k_gate<<<MT, 256>>>(x, out);
}